// round 15
// baseline (speedup 1.0000x reference)
#include <cuda_runtime.h>

#define BB 64
#define VV 2000
#define FF 8
#define GG 80
#define NRR 5               // distinct mu_rho  (g = r*16 + t)
#define NTT 16              // distinct mu_theta
#define NROT 5
#define NKG 3               // rotation groups: {0,1},{2,3},{4,4}
#define DD (FF*GG)          // 640
#define VCH 10              // vertex chunks per (b, kgroup)
#define VCS (VV/VCH)        // 200
#define NSLICE 4
#define TPB (GG*NSLICE)     // 320 threads kernel A
#define TPBB 256            // kernel B: 32 j-lanes x 8 i-segments
#define JT 20               // j tiles of 32
#define BG 32               // b groups of 2
#define TWO_PI_F 6.283185307179586f
#define EPSF 1e-5f
#define NLOG2E -1.4426950408889634f

// partial (unnormalized) sums: [bk][chunk][9][G]  (0: sum w; 1..8: sum w*feat)
__device__ float g_part[BB*NROT][VCH][9][GG];
// normalized descriptors: [bk][f*G+g]
__device__ __align__(16) float g_desc[BB*NROT][DD];

// ---------------- helpers ----------------
__device__ __forceinline__ unsigned long long pack2(float lo, float hi) {
    unsigned long long r;
    asm("mov.b64 %0, {%1, %2};" : "=l"(r) : "f"(lo), "f"(hi));
    return r;
}
__device__ __forceinline__ void fma2(unsigned long long& d,
                                     unsigned long long a, unsigned long long b) {
    asm("fma.rn.f32x2 %0, %1, %2, %3;" : "=l"(d) : "l"(a), "l"(b), "l"(d));
}
__device__ __forceinline__ void add2(unsigned long long& d, unsigned long long a) {
    asm("add.rn.f32x2 %0, %1, %2;" : "=l"(d) : "l"(d), "l"(a));
}
__device__ __forceinline__ float2 unpack2(unsigned long long v) {
    float lo, hi;
    asm("mov.b64 {%0, %1}, %2;" : "=f"(lo), "=f"(hi) : "l"(v));
    return make_float2(lo, hi);
}
__device__ __forceinline__ float ex2(float x) {
    float r;
    asm("ex2.approx.f32 %0, %1;" : "=f"(r) : "f"(x));
    return r;
}

// ---------------------------------------------------------------------------
// Kernel A: separable gaussians, TWO ROTATIONS per block (proven R12 form).
// T staged as float2{T_k0, T_k1}; rho gaussians, mask, feat shared across k.
// Inner per (v,g): LDS.64(T pair) + LDS.32(rv) + 2x LDS.128(feat); unroll 4.
// ---------------------------------------------------------------------------
__global__ void __launch_bounds__(TPB, 4)
gauss_desc_kernel(const float* __restrict__ feat,
                  const float* __restrict__ rho,
                  const float* __restrict__ theta,
                  const float* __restrict__ mask,
                  const float* __restrict__ mu_rho,
                  const float* __restrict__ sigma_rho,
                  const float* __restrict__ mu_theta,
                  const float* __restrict__ sigma_theta)
{
    extern __shared__ float sm[];
    float2* s_T2   = (float2*)sm;                  // [VCS*16]  25600 B
    float*  s_R    = sm + VCS*32;                  // [VCS*8]    6400 B (5 used)
    float*  s_feat = sm + VCS*40;                  // [VCS*8]    6400 B
    float2* s_th   = (float2*)(sm + VCS*48);       // [VCS]      1600 B
                                                   // total     40000 B

    const int bg  = blockIdx.x;
    const int b   = bg / NKG;
    const int kg  = bg - b*NKG;
    const int k0  = kg*2;
    const int k1  = (k0 + 1 < NROT) ? k0 + 1 : k0; // group 2 duplicates k=4
    const int cv0 = blockIdx.y * VCS;
    const int tid = threadIdx.x;
    const float kd0 = (float)k0 * (TWO_PI_F / (float)NROT);
    const float kd1 = (float)k1 * (TWO_PI_F / (float)NROT);

    // hoisted gaussian params (staging only)
    float mur[NRR], nisr[NRR];
    #pragma unroll
    for (int r = 0; r < NRR; r++) {
        float m = mu_rho[r*NTT];                   // grid: constant across t
        float s = sigma_rho[r*NTT];
        mur[r]  = m;
        nisr[r] = NLOG2E / (s*s + EPSF);
    }
    const int t0 = tid & 15;
    const float mut0  = mu_theta[t0];
    const float st0   = sigma_theta[t0];
    const float nist0 = NLOG2E / (st0*st0 + EPSF);

    // phase 1: per-vertex rotated thetas + 5 rho gaussians * mask + feat
    for (int v = tid; v < VCS; v += TPB) {
        float th  = theta[b*VV + cv0 + v];
        float a   = th + kd0; if (a >= TWO_PI_F) a -= TWO_PI_F;   // theta in [0,2pi)
        float c   = th + kd1; if (c >= TWO_PI_F) c -= TWO_PI_F;
        s_th[v] = make_float2(a, c);
        float rr = rho[b*VV + cv0 + v];
        float mk = mask[b*VV + cv0 + v];
        #pragma unroll
        for (int r = 0; r < NRR; r++) {
            float d = rr - mur[r];
            s_R[v*8 + r] = ex2(d*d * nisr[r]) * mk;
        }
    }
    for (int i = tid; i < VCS*FF/4; i += TPB)
        ((float4*)s_feat)[i] = ((const float4*)(feat + (size_t)(b*VV + cv0)*FF))[i];
    __syncthreads();

    // phase 2: theta gaussians for both rotations (t fixed per thread)
    for (int i = tid; i < VCS*NTT; i += TPB) {
        int v = i >> 4;
        float2 th = s_th[v];
        float d0 = th.x - mut0;
        float d1 = th.y - mut0;
        s_T2[i] = make_float2(ex2(d0*d0 * nist0), ex2(d1*d1 * nist0));
    }
    __syncthreads();

    const int g     = tid % GG;
    const int slice = tid / GG;
    const int r     = g >> 4;
    const int t     = g & 15;

    float a00 = 0.0f, a01 = 0.0f;
    unsigned long long acc0[4] = {0ull,0ull,0ull,0ull};
    unsigned long long acc1[4] = {0ull,0ull,0ull,0ull};

    #pragma unroll 4
    for (int v = slice; v < VCS; v += NSLICE) {
        float2 tv = s_T2[v*NTT + t];
        float  rv = s_R[v*8 + r];
        float w0 = tv.x * rv;
        float w1 = tv.y * rv;
        a00 += w0;
        a01 += w1;
        unsigned long long w20 = pack2(w0, w0);
        unsigned long long w21 = pack2(w1, w1);
        const ulonglong2* fp = (const ulonglong2*)(s_feat + v*FF);
        ulonglong2 q0 = fp[0];
        ulonglong2 q1 = fp[1];
        fma2(acc0[0], w20, q0.x); fma2(acc0[1], w20, q0.y);
        fma2(acc0[2], w20, q1.x); fma2(acc0[3], w20, q1.y);
        fma2(acc1[0], w21, q0.x); fma2(acc1[1], w21, q0.y);
        fma2(acc1[2], w21, q1.x); fma2(acc1[3], w21, q1.y);
    }
    __syncthreads();                    // vertex data dead; overlay reduction

    // packed reduction buffer: [320][10] ullong = 25600 B (fits in 40000)
    unsigned long long* redU = (unsigned long long*)sm;
    {
        unsigned long long* dst = redU + tid*10;
        #pragma unroll
        for (int p = 0; p < 4; p++) dst[p] = acc0[p];
        dst[4] = pack2(a00, a00);
        #pragma unroll
        for (int p = 0; p < 4; p++) dst[5 + p] = acc1[p];
        dst[9] = pack2(a01, a01);
    }
    __syncthreads();

    // combine 4 slices; outputs: 2 rotations x 5 packed items x 80 g
    for (int e = tid; e < 2*5*GG; e += TPB) {
        int kk   = e / (5*GG);                 // 0 -> k0, 1 -> k1
        int rem  = e - kk*(5*GG);
        int item = rem / GG;
        int gg   = rem - item*GG;
        if (kk == 1 && k1 == k0) continue;     // duplicated rotation group
        unsigned long long s = 0ull;
        #pragma unroll
        for (int sl = 0; sl < NSLICE; sl++)
            add2(s, redU[(sl*GG + gg)*10 + kk*5 + item]);
        float2 u = unpack2(s);
        int bk = b*NROT + (kk ? k1 : k0);
        if (item == 4) {
            g_part[bk][blockIdx.y][0][gg] = u.x;
        } else {
            g_part[bk][blockIdx.y][1 + 2*item][gg] = u.x;
            g_part[bk][blockIdx.y][2 + 2*item][gg] = u.y;
        }
    }
}

// ---------------------------------------------------------------------------
// Kernel A2: reduce chunks + normalize ONCE: g_part -> g_desc[bk][f*G+g].
// ---------------------------------------------------------------------------
__global__ void __launch_bounds__(GG)
normalize_kernel()
{
    const int bk = blockIdx.x;
    const int g  = threadIdx.x;
    float S[9];
    #pragma unroll
    for (int j = 0; j < 9; j++) S[j] = 0.0f;
    #pragma unroll
    for (int c = 0; c < VCH; c++)
        #pragma unroll
        for (int j = 0; j < 9; j++) S[j] += g_part[bk][c][j][g];
    float inv = 1.0f / (S[0] + EPSF);
    #pragma unroll
    for (int f = 0; f < FF; f++)
        g_desc[bk][f*GG + g] = S[1 + f] * inv;
}

// ---------------------------------------------------------------------------
// Kernel B: out[b,j] = relu(max_k desc_k@W[:,j] + bias[j]).
// 640 blocks (20 j-tiles x 32 b-pairs) x 256 threads (32 j x 8 i-segments).
// Contiguous desc prologue; 10 packed accs; packed segment combine.
// ---------------------------------------------------------------------------
__global__ void __launch_bounds__(TPBB)
gemm_max_relu_kernel(const float* __restrict__ Wm,
                     const float* __restrict__ bias,
                     float* __restrict__ out)
{
    __shared__ __align__(16) char smB[2*NROT*DD*4];    // 25600 B (union)
    float* s_desc = (float*)smB;                        // [10][640]
    unsigned long long* red = (unsigned long long*)smB; // [256][10] = 20480 B

    const int tid = threadIdx.x;
    const int b0  = blockIdx.y * 2;

    // rows bk = b0*5 .. b0*5+9 are contiguous in g_desc
    {
        const float4* src = (const float4*)g_desc[b0*NROT];
        float4* dst = (float4*)s_desc;
        for (int e = tid; e < 2*NROT*DD/4; e += TPBB)
            dst[e] = src[e];
    }
    __syncthreads();

    const int tx  = tid & 31;
    const int seg = tid >> 5;                     // one segment per warp
    const int j   = blockIdx.x * 32 + tx;
    const int i0  = seg * (DD/8);                 // 80-row segment

    unsigned long long acc[10];
    #pragma unroll
    for (int a = 0; a < 10; a++) acc[a] = 0ull;

    #pragma unroll 5
    for (int i = i0; i < i0 + DD/8; i += 4) {
        float w0 = Wm[(i+0)*DD + j];
        float w1 = Wm[(i+1)*DD + j];
        float w2 = Wm[(i+2)*DD + j];
        float w3 = Wm[(i+3)*DD + j];
        unsigned long long wp0 = pack2(w0, w1);
        unsigned long long wp1 = pack2(w2, w3);
        #pragma unroll
        for (int a = 0; a < 10; a++) {
            ulonglong2 d = *(const ulonglong2*)&s_desc[a*DD + i];
            fma2(acc[a], d.x, wp0);
            fma2(acc[a], d.y, wp1);
        }
    }
    __syncthreads();                               // everyone done reading desc

    #pragma unroll
    for (int a = 0; a < 10; a++) red[tid*10 + a] = acc[a];
    __syncthreads();

    if (tid < 32) {
        const float bj = bias[j];
        #pragma unroll
        for (int bb = 0; bb < 2; bb++) {
            float m = -3.4e38f;
            #pragma unroll
            for (int kk = 0; kk < NROT; kk++) {
                int a = bb*NROT + kk;
                unsigned long long s = red[tid*10 + a];
                #pragma unroll
                for (int sg = 1; sg < 8; sg++)
                    add2(s, red[(sg*32 + tid)*10 + a]);
                float2 u = unpack2(s);
                m = fmaxf(m, u.x + u.y);
            }
            out[(b0 + bb)*DD + j] = fmaxf(m + bj, 0.0f);
        }
    }
}

// ---------------------------------------------------------------------------

extern "C" void kernel_launch(void* const* d_in, const int* in_sizes, int n_in,
                              void* d_out, int out_size) {
    const float* feat        = (const float*)d_in[0];
    const float* rho         = (const float*)d_in[1];
    const float* theta       = (const float*)d_in[2];
    const float* mask        = (const float*)d_in[3];
    const float* mu_rho      = (const float*)d_in[4];
    const float* sigma_rho   = (const float*)d_in[5];
    const float* mu_theta    = (const float*)d_in[6];
    const float* sigma_theta = (const float*)d_in[7];
    const float* Wm          = (const float*)d_in[8];
    const float* bias        = (const float*)d_in[9];
    float* out = (float*)d_out;

    const int smemA = 40000;
    cudaFuncSetAttribute(gauss_desc_kernel,
                         cudaFuncAttributeMaxDynamicSharedMemorySize, smemA);

    gauss_desc_kernel<<<dim3(BB*NKG, VCH), TPB, smemA>>>(
        feat, rho, theta, mask, mu_rho, sigma_rho, mu_theta, sigma_theta);

    normalize_kernel<<<BB*NROT, GG>>>();

    gemm_max_relu_kernel<<<dim3(JT, BG), TPBB>>>(Wm, bias, out);
}

// round 17
// speedup vs baseline: 1.6475x; 1.6475x over previous
#include <cuda_runtime.h>

#define BB 64
#define VV 2000
#define FF 8
#define GG 80
#define NRR 5               // distinct mu_rho  (g = r*16 + t)
#define NTT 16              // distinct mu_theta
#define NROT 5
#define NKG 3               // rotation groups: {0,1},{2,3},{4,4}
#define DD (FF*GG)          // 640
#define VCH 10              // vertex chunks per (b, kgroup)
#define VCS (VV/VCH)        // 200
#define NSLICE 4
#define TPB (GG*NSLICE)     // 320 threads kernel A
#define TPBB 256            // kernel B: 64 j-lanes x 4 i-segments
#define JT 10               // j tiles of 64
#define BG 32               // b groups of 2
#define TWO_PI_F 6.283185307179586f
#define EPSF 1e-5f
#define NLOG2E -1.4426950408889634f

// partial (unnormalized) sums: [bk][chunk][9][G]  (0: sum w; 1..8: sum w*feat)
__device__ float g_part[BB*NROT][VCH][9][GG];
// normalized descriptors: [bk][f*G+g]
__device__ __align__(16) float g_desc[BB*NROT][DD];

// ---------------- helpers ----------------
__device__ __forceinline__ unsigned long long pack2(float lo, float hi) {
    unsigned long long r;
    asm("mov.b64 %0, {%1, %2};" : "=l"(r) : "f"(lo), "f"(hi));
    return r;
}
__device__ __forceinline__ void fma2(unsigned long long& d,
                                     unsigned long long a, unsigned long long b) {
    asm("fma.rn.f32x2 %0, %1, %2, %3;" : "=l"(d) : "l"(a), "l"(b), "l"(d));
}
__device__ __forceinline__ void add2(unsigned long long& d, unsigned long long a) {
    asm("add.rn.f32x2 %0, %1, %2;" : "=l"(d) : "l"(d), "l"(a));
}
__device__ __forceinline__ float2 unpack2(unsigned long long v) {
    float lo, hi;
    asm("mov.b64 {%0, %1}, %2;" : "=f"(lo), "=f"(hi) : "l"(v));
    return make_float2(lo, hi);
}
__device__ __forceinline__ float ex2(float x) {
    float r;
    asm("ex2.approx.f32 %0, %1;" : "=f"(r) : "f"(x));
    return r;
}

// ---------------------------------------------------------------------------
// Kernel A: separable gaussians, TWO ROTATIONS per block (exact R12 form,
// measured 40.4us). T staged as float2{T_k0, T_k1}; rho gaussians, mask,
// feat shared across k. Default unrolling (unroll pragmas regress this loop).
// ---------------------------------------------------------------------------
__global__ void __launch_bounds__(TPB, 4)
gauss_desc_kernel(const float* __restrict__ feat,
                  const float* __restrict__ rho,
                  const float* __restrict__ theta,
                  const float* __restrict__ mask,
                  const float* __restrict__ mu_rho,
                  const float* __restrict__ sigma_rho,
                  const float* __restrict__ mu_theta,
                  const float* __restrict__ sigma_theta)
{
    extern __shared__ float sm[];
    float2* s_T2   = (float2*)sm;                  // [VCS*16]  25600 B
    float*  s_R    = sm + VCS*32;                  // [VCS*8]    6400 B (5 used)
    float*  s_feat = sm + VCS*40;                  // [VCS*8]    6400 B
    float2* s_th   = (float2*)(sm + VCS*48);       // [VCS]      1600 B
                                                   // total     40000 B

    const int bg  = blockIdx.x;
    const int b   = bg / NKG;
    const int kg  = bg - b*NKG;
    const int k0  = kg*2;
    const int k1  = (k0 + 1 < NROT) ? k0 + 1 : k0; // group 2 duplicates k=4
    const int cv0 = blockIdx.y * VCS;
    const int tid = threadIdx.x;
    const float kd0 = (float)k0 * (TWO_PI_F / (float)NROT);
    const float kd1 = (float)k1 * (TWO_PI_F / (float)NROT);

    // hoisted gaussian params (staging only)
    float mur[NRR], nisr[NRR];
    #pragma unroll
    for (int r = 0; r < NRR; r++) {
        float m = mu_rho[r*NTT];                   // grid: constant across t
        float s = sigma_rho[r*NTT];
        mur[r]  = m;
        nisr[r] = NLOG2E / (s*s + EPSF);
    }
    const int t0 = tid & 15;
    const float mut0  = mu_theta[t0];
    const float st0   = sigma_theta[t0];
    const float nist0 = NLOG2E / (st0*st0 + EPSF);

    // phase 1: per-vertex rotated thetas + 5 rho gaussians * mask + feat
    for (int v = tid; v < VCS; v += TPB) {
        float th  = theta[b*VV + cv0 + v];
        float a   = th + kd0; if (a >= TWO_PI_F) a -= TWO_PI_F;   // theta in [0,2pi)
        float c   = th + kd1; if (c >= TWO_PI_F) c -= TWO_PI_F;
        s_th[v] = make_float2(a, c);
        float rr = rho[b*VV + cv0 + v];
        float mk = mask[b*VV + cv0 + v];
        #pragma unroll
        for (int r = 0; r < NRR; r++) {
            float d = rr - mur[r];
            s_R[v*8 + r] = ex2(d*d * nisr[r]) * mk;
        }
    }
    for (int i = tid; i < VCS*FF/4; i += TPB)
        ((float4*)s_feat)[i] = ((const float4*)(feat + (size_t)(b*VV + cv0)*FF))[i];
    __syncthreads();

    // phase 2: theta gaussians for both rotations (t fixed per thread)
    for (int i = tid; i < VCS*NTT; i += TPB) {
        int v = i >> 4;
        float2 th = s_th[v];
        float d0 = th.x - mut0;
        float d1 = th.y - mut0;
        s_T2[i] = make_float2(ex2(d0*d0 * nist0), ex2(d1*d1 * nist0));
    }
    __syncthreads();

    const int g     = tid % GG;
    const int slice = tid / GG;
    const int r     = g >> 4;
    const int t     = g & 15;

    float a00 = 0.0f, a01 = 0.0f;
    unsigned long long acc0[4] = {0ull,0ull,0ull,0ull};
    unsigned long long acc1[4] = {0ull,0ull,0ull,0ull};

    for (int v = slice; v < VCS; v += NSLICE) {
        float2 tv = s_T2[v*NTT + t];
        float  rv = s_R[v*8 + r];
        float w0 = tv.x * rv;
        float w1 = tv.y * rv;
        a00 += w0;
        a01 += w1;
        unsigned long long w20 = pack2(w0, w0);
        unsigned long long w21 = pack2(w1, w1);
        const ulonglong2* fp = (const ulonglong2*)(s_feat + v*FF);
        ulonglong2 q0 = fp[0];
        ulonglong2 q1 = fp[1];
        fma2(acc0[0], w20, q0.x); fma2(acc0[1], w20, q0.y);
        fma2(acc0[2], w20, q1.x); fma2(acc0[3], w20, q1.y);
        fma2(acc1[0], w21, q0.x); fma2(acc1[1], w21, q0.y);
        fma2(acc1[2], w21, q1.x); fma2(acc1[3], w21, q1.y);
    }
    __syncthreads();                    // vertex data dead; overlay reduction

    // packed reduction buffer: [320][10] ullong = 25600 B (fits in 40000)
    unsigned long long* redU = (unsigned long long*)sm;
    {
        unsigned long long* dst = redU + tid*10;
        #pragma unroll
        for (int p = 0; p < 4; p++) dst[p] = acc0[p];
        dst[4] = pack2(a00, a00);
        #pragma unroll
        for (int p = 0; p < 4; p++) dst[5 + p] = acc1[p];
        dst[9] = pack2(a01, a01);
    }
    __syncthreads();

    // combine 4 slices; outputs: 2 rotations x 5 packed items x 80 g
    for (int e = tid; e < 2*5*GG; e += TPB) {
        int kk   = e / (5*GG);                 // 0 -> k0, 1 -> k1
        int rem  = e - kk*(5*GG);
        int item = rem / GG;
        int gg   = rem - item*GG;
        if (kk == 1 && k1 == k0) continue;     // duplicated rotation group
        unsigned long long s = 0ull;
        #pragma unroll
        for (int sl = 0; sl < NSLICE; sl++)
            add2(s, redU[(sl*GG + gg)*10 + kk*5 + item]);
        float2 u = unpack2(s);
        int bk = b*NROT + (kk ? k1 : k0);
        if (item == 4) {
            g_part[bk][blockIdx.y][0][gg] = u.x;
        } else {
            g_part[bk][blockIdx.y][1 + 2*item][gg] = u.x;
            g_part[bk][blockIdx.y][2 + 2*item][gg] = u.y;
        }
    }
}

// ---------------------------------------------------------------------------
// Kernel A2: reduce chunks + normalize ONCE: g_part -> g_desc[bk][f*G+g].
// ---------------------------------------------------------------------------
__global__ void __launch_bounds__(GG)
normalize_kernel()
{
    const int bk = blockIdx.x;
    const int g  = threadIdx.x;
    float S[9];
    #pragma unroll
    for (int j = 0; j < 9; j++) S[j] = 0.0f;
    #pragma unroll
    for (int c = 0; c < VCH; c++)
        #pragma unroll
        for (int j = 0; j < 9; j++) S[j] += g_part[bk][c][j][g];
    float inv = 1.0f / (S[0] + EPSF);
    #pragma unroll
    for (int f = 0; f < FF; f++)
        g_desc[bk][f*GG + g] = S[1 + f] * inv;
}

// ---------------------------------------------------------------------------
// Kernel B: out[b,j] = relu(max_k desc_k@W[:,j] + bias[j]).
// 320 blocks (10 j-tiles x 32 b-pairs) x 256 threads (64 j x 4 i-segments)
// — the measured-best B config. Contiguous desc prologue; 10 packed accs.
// ---------------------------------------------------------------------------
__global__ void __launch_bounds__(TPBB)
gemm_max_relu_kernel(const float* __restrict__ Wm,
                     const float* __restrict__ bias,
                     float* __restrict__ out)
{
    __shared__ __align__(16) char smB[2*NROT*DD*4];    // 25600 B (union)
    float* s_desc = (float*)smB;                        // [10][640]
    unsigned long long* red = (unsigned long long*)smB; // [256][10] = 20480 B

    const int tid = threadIdx.x;
    const int b0  = blockIdx.y * 2;

    // rows bk = b0*5 .. b0*5+9 are contiguous in g_desc
    {
        const float4* src = (const float4*)g_desc[b0*NROT];
        float4* dst = (float4*)s_desc;
        for (int e = tid; e < 2*NROT*DD/4; e += TPBB)
            dst[e] = src[e];
    }
    __syncthreads();

    const int tx  = tid & 63;
    const int seg = tid >> 6;
    const int j   = blockIdx.x * 64 + tx;
    const int i0  = seg * (DD/4);                 // 160-row segment

    unsigned long long acc[10];
    #pragma unroll
    for (int a = 0; a < 10; a++) acc[a] = 0ull;

    #pragma unroll 8
    for (int i = i0; i < i0 + DD/4; i += 4) {
        float w0 = Wm[(i+0)*DD + j];
        float w1 = Wm[(i+1)*DD + j];
        float w2 = Wm[(i+2)*DD + j];
        float w3 = Wm[(i+3)*DD + j];
        unsigned long long wp0 = pack2(w0, w1);
        unsigned long long wp1 = pack2(w2, w3);
        #pragma unroll
        for (int a = 0; a < 10; a++) {
            ulonglong2 d = *(const ulonglong2*)&s_desc[a*DD + i];
            fma2(acc[a], d.x, wp0);
            fma2(acc[a], d.y, wp1);
        }
    }
    __syncthreads();                               // everyone done reading desc

    #pragma unroll
    for (int a = 0; a < 10; a++) red[tid*10 + a] = acc[a];
    __syncthreads();

    if (tid < 64) {
        const float bj = bias[j];
        #pragma unroll
        for (int bb = 0; bb < 2; bb++) {
            float m = -3.4e38f;
            #pragma unroll
            for (int kk = 0; kk < NROT; kk++) {
                int a = bb*NROT + kk;
                unsigned long long s = red[tid*10 + a];
                add2(s, red[(64  + tid)*10 + a]);
                add2(s, red[(128 + tid)*10 + a]);
                add2(s, red[(192 + tid)*10 + a]);
                float2 u = unpack2(s);
                m = fmaxf(m, u.x + u.y);
            }
            out[(b0 + bb)*DD + j] = fmaxf(m + bj, 0.0f);
        }
    }
}

// ---------------------------------------------------------------------------

extern "C" void kernel_launch(void* const* d_in, const int* in_sizes, int n_in,
                              void* d_out, int out_size) {
    const float* feat        = (const float*)d_in[0];
    const float* rho         = (const float*)d_in[1];
    const float* theta       = (const float*)d_in[2];
    const float* mask        = (const float*)d_in[3];
    const float* mu_rho      = (const float*)d_in[4];
    const float* sigma_rho   = (const float*)d_in[5];
    const float* mu_theta    = (const float*)d_in[6];
    const float* sigma_theta = (const float*)d_in[7];
    const float* Wm          = (const float*)d_in[8];
    const float* bias        = (const float*)d_in[9];
    float* out = (float*)d_out;

    const int smemA = 40000;
    cudaFuncSetAttribute(gauss_desc_kernel,
                         cudaFuncAttributeMaxDynamicSharedMemorySize, smemA);

    gauss_desc_kernel<<<dim3(BB*NKG, VCH), TPB, smemA>>>(
        feat, rho, theta, mask, mu_rho, sigma_rho, mu_theta, sigma_theta);

    normalize_kernel<<<BB*NROT, GG>>>();

    gemm_max_relu_kernel<<<dim3(JT, BG), TPBB>>>(Wm, bias, out);
}